// round 1
// baseline (speedup 1.0000x reference)
#include <cuda_runtime.h>
#include <cstdint>
#include <cstddef>

#define B       256
#define NIN     1152
#define NOUT    10
#define DOUT    16
#define DIN     8
#define OJ      160        // NOUT*DOUT
#define BT      32         // batch tile per CTA
#define BPAIRS  16         // BT/2
#define NCH     36         // n-chunks
#define NPER    32         // NIN / NCH
#define NTHREADS 320       // pass kernel threads (160 oj-slots x 2 bp-halves)

typedef unsigned long long u64;

// ------------------------------------------------------------------
// scratch (no allocations allowed -> __device__ globals)
// ------------------------------------------------------------------
__device__ float g_partial[NCH][B][OJ];   // per-chunk partial s  (5.9 MB)
__device__ float g_vsum[B][OJ];           // cumulative sum of v over rounds

// ------------------------------------------------------------------
// packed f32x2 helpers (sm_100+)
// ------------------------------------------------------------------
__device__ __forceinline__ u64 fma2(u64 a, u64 b, u64 c) {
    u64 d; asm("fma.rn.f32x2 %0,%1,%2,%3;" : "=l"(d) : "l"(a), "l"(b), "l"(c)); return d;
}
__device__ __forceinline__ u64 mul2(u64 a, u64 b) {
    u64 d; asm("mul.rn.f32x2 %0,%1,%2;" : "=l"(d) : "l"(a), "l"(b)); return d;
}
__device__ __forceinline__ u64 add2(u64 a, u64 b) {
    u64 d; asm("add.rn.f32x2 %0,%1,%2;" : "=l"(d) : "l"(a), "l"(b)); return d;
}
__device__ __forceinline__ u64 pk2(float lo, float hi) {
    u64 d; asm("mov.b64 %0,{%1,%2};" : "=l"(d) : "f"(lo), "f"(hi)); return d;
}
__device__ __forceinline__ void upk2(u64 v, float& lo, float& hi) {
    asm("mov.b64 {%0,%1},%2;" : "=f"(lo), "=f"(hi) : "l"(v));
}

// ------------------------------------------------------------------
// Pass kernel: for one routing round, accumulate partial
//   s[b][o][j] = sum_{n in chunk} c[b][n][o] * u_hat[b][n][o][j]
// where u_hat is recomputed on the fly and
//   c = softmax_o( u_hat . vsum )     (round>0)
//   c = 1/10  (uniform, applied as 0.1 scale at writeout)  (round 0)
//
// Thread layout: t in [0,320): oj = t%160 (o = oj/16, j = oj%16),
//                h = t/160 selects bp in [8h, 8h+8) (bp = batch pair).
// Reduce-phase layout: ro = t/32 in [0,10), rb = t%32.
// ------------------------------------------------------------------
template<int ROUND>
__global__ void __launch_bounds__(NTHREADS, 2)
pass_kernel(const float* __restrict__ x, const float* __restrict__ W)
{
    const int nc = blockIdx.x;            // n-chunk
    const int b0 = blockIdx.y * BT;       // batch base
    const int t  = threadIdx.x;
    const int p  = t % OJ;                // oj slot
    const int h  = t / OJ;                // 0 or 1 -> bp half
    const int o  = p >> 4;                // capsule-out index of this oj
    const int ro = t >> 5;                // reduce phase: o index (0..9, exact)
    const int rb = t & 31;                // reduce phase: b index

    // shared: W duplicated into f32x2 pairs, padded to 9 u64/row (conflict-free)
    __shared__ u64   W2s[OJ][9];          // [oj][i] = {w,w}            11.25 KB
    __shared__ float x2f[DIN][BT];        // [i][b], pairs contiguous    1 KB
    __shared__ float p_s[OJ][BT + 2];     // agreement partials (pad 34) 21.25 KB
    __shared__ float e_s[NOUT][BT];       // exp(agreement)              1.25 KB
    __shared__ float r_s[BT];             // 1/sum of exps per b

    u64 s2[8];                            // s accumulator, one per bp
    #pragma unroll
    for (int k = 0; k < 8; ++k) s2[k] = 0ULL;

    u64 vs2[8];                           // vsum pairs for this oj / bps
    if (ROUND > 0) {
        #pragma unroll
        for (int k = 0; k < 8; ++k) {
            const int b = b0 + 2 * (h * 8 + k);
            vs2[k] = pk2(g_vsum[b][p], g_vsum[b + 1][p]);
        }
    }

    for (int nn = 0; nn < NPER; ++nn) {
        const int n = nc * NPER + nn;

        // ---- cooperative load: W[n] (1280 floats) transposed+duplicated ----
        {
            const float4* Wg = reinterpret_cast<const float4*>(
                W + (size_t)n * (NOUT * DIN * DOUT));
            float4 w4 = Wg[t];                 // 320 threads x float4 = 1280 floats
            const int lo = t >> 5;             // o of this quad
            const int li = (t >> 2) & 7;       // i
            const int jq = t & 3;              // j-quad
            const int r  = lo * 16 + jq * 4;
            W2s[r + 0][li] = pk2(w4.x, w4.x);
            W2s[r + 1][li] = pk2(w4.y, w4.y);
            W2s[r + 2][li] = pk2(w4.z, w4.z);
            W2s[r + 3][li] = pk2(w4.w, w4.w);
        }
        // ---- cooperative load: x[b0..b0+31][n][0..7] transposed to [i][b] ----
        if (t < 64) {
            const int b = t >> 1, half = t & 1;
            float4 xv = reinterpret_cast<const float4*>(
                x + ((size_t)(b0 + b) * NIN + n) * DIN)[half];
            x2f[half * 4 + 0][b] = xv.x;
            x2f[half * 4 + 1][b] = xv.y;
            x2f[half * 4 + 2][b] = xv.z;
            x2f[half * 4 + 3][b] = xv.w;
        }
        __syncthreads();

        // ---- u_hat for this oj over 8 batch-pairs (packed f32x2) ----
        u64 wr[8];
        #pragma unroll
        for (int i = 0; i < 8; ++i) wr[i] = W2s[p][i];

        u64 u2[8];
        #pragma unroll
        for (int k = 0; k < 8; ++k) {
            const int bp = h * 8 + k;
            u64 acc = 0ULL;
            #pragma unroll
            for (int i = 0; i < 8; ++i) {
                u64 xv = *reinterpret_cast<const u64*>(&x2f[i][2 * bp]);
                acc = fma2(wr[i], xv, acc);
            }
            u2[k] = acc;
        }

        if (ROUND == 0) {
            #pragma unroll
            for (int k = 0; k < 8; ++k) s2[k] = add2(s2[k], u2[k]);
            __syncthreads();           // protect W2s/x2f before next iter's load
        } else {
            // ---- agreement partial products -> p_s[oj][b] ----
            #pragma unroll
            for (int k = 0; k < 8; ++k) {
                const int bp = h * 8 + k;
                *reinterpret_cast<u64*>(&p_s[p][2 * bp]) = mul2(u2[k], vs2[k]);
            }
            __syncthreads();
            // ---- reduce over j (16) and exponentiate; (ro,rb) covers 10x32 ----
            {
                float a = 0.f;
                #pragma unroll
                for (int j = 0; j < 16; ++j) a += p_s[ro * 16 + j][rb];
                // |a| is tiny (<~0.3): plain exp matches softmax-with-max exactly
                e_s[ro][rb] = __expf(a);
            }
            __syncthreads();
            // ---- per-b reciprocal of softmax denominator ----
            if (t < BT) {
                float ssum = 0.f;
                #pragma unroll
                for (int oo = 0; oo < NOUT; ++oo) ssum += e_s[oo][t];
                r_s[t] = 1.0f / ssum;
            }
            __syncthreads();
            // ---- reweight: s += c * u_hat,  c = e * (1/sum) ----
            #pragma unroll
            for (int k = 0; k < 8; ++k) {
                const int bp = h * 8 + k;
                u64 rs = *reinterpret_cast<const u64*>(&r_s[2 * bp]);
                u64 ev = *reinterpret_cast<const u64*>(&e_s[o][2 * bp]);
                s2[k] = fma2(mul2(ev, rs), u2[k], s2[k]);
            }
            __syncthreads();
        }
    }

    // ---- write per-chunk partial s (deterministic; no atomics) ----
    const float scale = (ROUND == 0) ? 0.1f : 1.0f;
    #pragma unroll
    for (int k = 0; k < 8; ++k) {
        const int b = b0 + 2 * (h * 8 + k);
        float lo, hi;
        upk2(s2[k], lo, hi);
        g_partial[nc][b][p]     = lo * scale;
        g_partial[nc][b + 1][p] = hi * scale;
    }
}

// ------------------------------------------------------------------
// Squash kernel: reduce 36 chunk partials, squash per (b,o),
// maintain vsum (cumulative v) or emit final output.
// One block per b, 160 threads (t = o*16 + j).
// ------------------------------------------------------------------
template<int ROUND>
__global__ void __launch_bounds__(OJ)
squash_kernel(float* __restrict__ out)
{
    const int b = blockIdx.x;
    const int t = threadIdx.x;

    float s = 0.f;
    #pragma unroll
    for (int c = 0; c < NCH; ++c) s += g_partial[c][b][t];

    // norm_sq over j: 16-lane aligned groups within the warp
    float nsq = s * s;
    #pragma unroll
    for (int m = 1; m < 16; m <<= 1)
        nsq += __shfl_xor_sync(0xffffffffu, nsq, m);

    const float norm = sqrtf(nsq + 1e-9f);
    const float v = s * (nsq / ((1.0f + nsq) * norm));

    if (ROUND == 0)       g_vsum[b][t] = v;
    else if (ROUND == 1)  g_vsum[b][t] += v;
    else                  out[(size_t)b * OJ + t] = v;
}

// ------------------------------------------------------------------
extern "C" void kernel_launch(void* const* d_in, const int* in_sizes, int n_in,
                              void* d_out, int out_size)
{
    const float* a0 = (const float*)d_in[0];
    const float* a1 = (const float*)d_in[1];
    const float* x;
    const float* W;
    if (in_sizes[0] == B * NIN * DIN) { x = a0; W = a1; }
    else                              { x = a1; W = a0; }
    float* out = (float*)d_out;

    dim3 pg(NCH, B / BT);   // 36 x 8 = 288 CTAs

    pass_kernel<0><<<pg, NTHREADS>>>(x, W);
    squash_kernel<0><<<B, OJ>>>(out);
    pass_kernel<1><<<pg, NTHREADS>>>(x, W);
    squash_kernel<1><<<B, OJ>>>(out);
    pass_kernel<2><<<pg, NTHREADS>>>(x, W);
    squash_kernel<2><<<B, OJ>>>(out);
}

// round 4
// speedup vs baseline: 1.1026x; 1.1026x over previous
#include <cuda_runtime.h>
#include <cstdint>
#include <cstddef>

#define B       256
#define NIN     1152
#define NOUT    10
#define DOUT    16
#define DIN     8
#define OJ      160        // NOUT*DOUT
#define BT      32         // batch tile per CTA
#define NCH     36         // n-chunks
#define NPER    32         // NIN / NCH
#define NT      320        // pass kernel threads

typedef unsigned long long u64;

// ------------------------------------------------------------------
// scratch (no allocations allowed -> __device__ globals)
// ------------------------------------------------------------------
__device__ float g_partial[NCH][B][OJ];   // per-chunk partial s (5.9 MB)
__device__ float g_vsum[B][OJ];           // cumulative v over rounds

// ------------------------------------------------------------------
// packed f32x2 helpers (sm_100+)
// ------------------------------------------------------------------
__device__ __forceinline__ u64 fma2(u64 a, u64 b, u64 c) {
    u64 d; asm("fma.rn.f32x2 %0,%1,%2,%3;" : "=l"(d) : "l"(a), "l"(b), "l"(c)); return d;
}
__device__ __forceinline__ u64 mul2(u64 a, u64 b) {
    u64 d; asm("mul.rn.f32x2 %0,%1,%2;" : "=l"(d) : "l"(a), "l"(b)); return d;
}
__device__ __forceinline__ u64 add2(u64 a, u64 b) {
    u64 d; asm("add.rn.f32x2 %0,%1,%2;" : "=l"(d) : "l"(a), "l"(b)); return d;
}
__device__ __forceinline__ u64 pk2(float lo, float hi) {
    u64 d; asm("mov.b64 %0,{%1,%2};" : "=l"(d) : "f"(lo), "f"(hi)); return d;
}
__device__ __forceinline__ void upk2(u64 v, float& lo, float& hi) {
    asm("mov.b64 {%0,%1},%2;" : "=f"(lo), "=f"(hi) : "l"(v));
}

// ------------------------------------------------------------------
// Pass kernel (one routing round): accumulate per-chunk partial
//   s[b][o][j] = sum_{n in chunk} c[b][n][o] * u_hat[b][n][o][j]
// u_hat recomputed on the fly; c = softmax_o(u_hat . vsum) (round>0),
// uniform 0.1 (round 0, folded in at writeout).
//
// Threads: t in [0,320): p = t%160 (oj slot: o=p/16, j=p%16),
//          h = t/160 -> batch pairs [8h, 8h+8).
// Pipelining: W[n+1]/x[n+1] LDG issued at iter top into regs,
// STS into the alternate SMEM buffer overlapped with the r_s phase.
// ------------------------------------------------------------------
template<int ROUND>
__global__ void __launch_bounds__(NT, 2)
pass_kernel(const float* __restrict__ x, const float* __restrict__ W)
{
    const int nc = blockIdx.x;
    const int b0 = blockIdx.y * BT;
    const int t  = threadIdx.x;
    const int p  = t % OJ;
    const int h  = t / OJ;
    const int o  = p >> 4;
    const int ro = t >> 5;          // reduce phase: o (0..9 exact)
    const int rb = t & 31;          // reduce phase: b

    // W store mapping: float4 index t covers W[n][o][i][j..j+3]
    const int wi   = (t >> 2) & 7;              // i
    const int wcol = (t >> 5) * 16 + (t & 3) * 4; // o*16 + j

    // x load mapping (t<64): b = t/2, half = t&1
    const int xb = t >> 1;
    const int xh = t & 1;

    __shared__ __align__(16) u64   W2s[2][DIN][OJ + 1]; // [buf][i][oj]={w,w} 20.1KB
    __shared__ __align__(16) float x2f[2][DIN][BT];     // [buf][i][b]        2KB
    __shared__ __align__(16) float p_s[OJ][BT + 2];     // agreement partials 21.25KB
    __shared__ __align__(16) float e_s[NOUT][BT];       // exp(agreement)
    __shared__ __align__(16) float r_s[BT];             // 1/sum_o exp

    const float4* __restrict__ Wg = reinterpret_cast<const float4*>(W);
    const float4* __restrict__ xrow =
        reinterpret_cast<const float4*>(x + (size_t)(b0 + xb) * NIN * DIN);

    u64 s2[8];
    #pragma unroll
    for (int k = 0; k < 8; ++k) s2[k] = 0ULL;

    u64 vs2[8];
    if (ROUND > 0) {
        #pragma unroll
        for (int k = 0; k < 8; ++k) {
            const int b = b0 + 2 * (h * 8 + k);
            vs2[k] = pk2(g_vsum[b][p], g_vsum[b + 1][p]);
        }
    }

    const int nbase = nc * NPER;

    // ---- prologue: load + stage n=0 into buffer 0 ----
    float4 w4 = Wg[(size_t)nbase * 320 + t];
    float4 xv;
    if (t < 64) xv = xrow[(size_t)nbase * 2 + xh];
    W2s[0][wi][wcol + 0] = pk2(w4.x, w4.x);
    W2s[0][wi][wcol + 1] = pk2(w4.y, w4.y);
    W2s[0][wi][wcol + 2] = pk2(w4.z, w4.z);
    W2s[0][wi][wcol + 3] = pk2(w4.w, w4.w);
    if (t < 64) {
        x2f[0][xh * 4 + 0][xb] = xv.x;
        x2f[0][xh * 4 + 1][xb] = xv.y;
        x2f[0][xh * 4 + 2][xb] = xv.z;
        x2f[0][xh * 4 + 3][xb] = xv.w;
    }
    __syncthreads();

    for (int nn = 0; nn < NPER; ++nn) {
        const int buf  = nn & 1;
        const int nbuf = buf ^ 1;

        // ---- prefetch n+1 (clamped) into registers ----
        const int n1 = nbase + ((nn + 1 < NPER) ? nn + 1 : nn);
        w4 = Wg[(size_t)n1 * 320 + t];
        if (t < 64) xv = xrow[(size_t)n1 * 2 + xh];

        // ---- u_hat for this oj over 8 batch pairs (packed f32x2) ----
        u64 u2[8];
        #pragma unroll
        for (int k = 0; k < 8; ++k) u2[k] = 0ULL;
        #pragma unroll
        for (int i = 0; i < 8; ++i) {
            const u64 wr = W2s[buf][i][p];
            const ulonglong2* xp =
                reinterpret_cast<const ulonglong2*>(&x2f[buf][i][h * 16]);
            #pragma unroll
            for (int q = 0; q < 4; ++q) {
                ulonglong2 xq = xp[q];
                u2[2 * q]     = fma2(wr, xq.x, u2[2 * q]);
                u2[2 * q + 1] = fma2(wr, xq.y, u2[2 * q + 1]);
            }
        }

        if (ROUND == 0) {
            #pragma unroll
            for (int k = 0; k < 8; ++k) s2[k] = add2(s2[k], u2[k]);
            // stage n+1 into the other buffer
            W2s[nbuf][wi][wcol + 0] = pk2(w4.x, w4.x);
            W2s[nbuf][wi][wcol + 1] = pk2(w4.y, w4.y);
            W2s[nbuf][wi][wcol + 2] = pk2(w4.z, w4.z);
            W2s[nbuf][wi][wcol + 3] = pk2(w4.w, w4.w);
            if (t < 64) {
                x2f[nbuf][xh * 4 + 0][xb] = xv.x;
                x2f[nbuf][xh * 4 + 1][xb] = xv.y;
                x2f[nbuf][xh * 4 + 2][xb] = xv.z;
                x2f[nbuf][xh * 4 + 3][xb] = xv.w;
            }
            __syncthreads();
        } else {
            // ---- agreement partial products ----
            #pragma unroll
            for (int k = 0; k < 8; ++k)
                *reinterpret_cast<u64*>(&p_s[p][2 * (h * 8 + k)]) =
                    mul2(u2[k], vs2[k]);
            __syncthreads();

            // ---- reduce over j + exp; (ro,rb) covers 10x32 exactly ----
            {
                float a = 0.f;
                #pragma unroll
                for (int j = 0; j < 16; ++j) a += p_s[ro * 16 + j][rb];
                e_s[ro][rb] = __expf(a);   // |a| tiny -> matches max-shifted softmax
            }
            __syncthreads();

            // ---- r_s by one warp; everyone else stages n+1 under it ----
            if (t < BT) {
                float ssum = 0.f;
                #pragma unroll
                for (int oo = 0; oo < NOUT; ++oo) ssum += e_s[oo][t];
                r_s[t] = 1.0f / ssum;
            }
            W2s[nbuf][wi][wcol + 0] = pk2(w4.x, w4.x);
            W2s[nbuf][wi][wcol + 1] = pk2(w4.y, w4.y);
            W2s[nbuf][wi][wcol + 2] = pk2(w4.z, w4.z);
            W2s[nbuf][wi][wcol + 3] = pk2(w4.w, w4.w);
            if (t < 64) {
                x2f[nbuf][xh * 4 + 0][xb] = xv.x;
                x2f[nbuf][xh * 4 + 1][xb] = xv.y;
                x2f[nbuf][xh * 4 + 2][xb] = xv.z;
                x2f[nbuf][xh * 4 + 3][xb] = xv.w;
            }
            __syncthreads();

            // ---- reweight: s += c * u_hat ----
            #pragma unroll
            for (int k = 0; k < 8; ++k) {
                const int bp2 = 2 * (h * 8 + k);
                u64 ev = *reinterpret_cast<const u64*>(&e_s[o][bp2]);
                u64 rv = *reinterpret_cast<const u64*>(&r_s[bp2]);
                s2[k] = fma2(mul2(ev, rv), u2[k], s2[k]);
            }
            // no trailing barrier: next writes to e_s/r_s/p_s are all
            // separated from these reads by >=1 barrier in the next iter.
        }
    }

    // ---- write per-chunk partial (deterministic, no atomics) ----
    const float scale = (ROUND == 0) ? 0.1f : 1.0f;
    #pragma unroll
    for (int k = 0; k < 8; ++k) {
        const int b = b0 + 2 * (h * 8 + k);
        float lo, hi;
        upk2(s2[k], lo, hi);
        g_partial[nc][b][p]     = lo * scale;
        g_partial[nc][b + 1][p] = hi * scale;
    }
}

// ------------------------------------------------------------------
// Squash: reduce 36 chunk partials (3-way thread split for MLP),
// squash per (b,o), maintain cumulative vsum / emit final output.
// ------------------------------------------------------------------
template<int ROUND>
__global__ void __launch_bounds__(3 * OJ)
squash_kernel(float* __restrict__ out)
{
    const int b  = blockIdx.x;
    const int t  = threadIdx.x;
    const int g  = t / OJ;          // 0..2
    const int tt = t % OJ;

    __shared__ float red[3][OJ];

    float s = 0.f;
    #pragma unroll
    for (int c = 0; c < NCH / 3; ++c) s += g_partial[c * 3 + g][b][tt];
    red[g][tt] = s;
    __syncthreads();

    if (t < OJ) {
        const float sv = red[0][t] + red[1][t] + red[2][t];

        float nsq = sv * sv;
        #pragma unroll
        for (int m = 1; m < 16; m <<= 1)
            nsq += __shfl_xor_sync(0xffffffffu, nsq, m);

        const float norm = sqrtf(nsq + 1e-9f);
        const float v = sv * (nsq / ((1.0f + nsq) * norm));

        if (ROUND == 0)       g_vsum[b][t] = v;
        else if (ROUND == 1)  g_vsum[b][t] += v;
        else                  out[(size_t)b * OJ + t] = v;
    }
}

// ------------------------------------------------------------------
extern "C" void kernel_launch(void* const* d_in, const int* in_sizes, int n_in,
                              void* d_out, int out_size)
{
    const float* a0 = (const float*)d_in[0];
    const float* a1 = (const float*)d_in[1];
    const float* x;
    const float* W;
    if (in_sizes[0] == B * NIN * DIN) { x = a0; W = a1; }
    else                              { x = a1; W = a0; }
    float* out = (float*)d_out;

    dim3 pg(NCH, B / BT);   // 36 x 8 = 288 CTAs

    pass_kernel<0><<<pg, NT>>>(x, W);
    squash_kernel<0><<<B, 3 * OJ>>>(out);
    pass_kernel<1><<<pg, NT>>>(x, W);
    squash_kernel<1><<<B, 3 * OJ>>>(out);
    pass_kernel<2><<<pg, NT>>>(x, W);
    squash_kernel<2><<<B, 3 * OJ>>>(out);
}

// round 5
// speedup vs baseline: 1.1032x; 1.0006x over previous
#include <cuda_runtime.h>
#include <cstdint>
#include <cstddef>

#define B       256
#define NIN     1152
#define NOUT    10
#define DOUT    16
#define DIN     8
#define OJ      160        // NOUT*DOUT
#define BT      32         // batch tile per CTA
#define NCH     36         // n-chunks
#define NPER    32         // NIN / NCH
#define NT      320        // pass kernel threads

typedef unsigned long long u64;

// ------------------------------------------------------------------
// scratch (no allocations allowed -> __device__ globals)
// ------------------------------------------------------------------
__device__ float g_partial[NCH][B][OJ];   // per-chunk partial s (5.9 MB)
__device__ float g_vsum[B][OJ];           // cumulative v over rounds

// ------------------------------------------------------------------
// packed f32x2 helpers (sm_100+)
// ------------------------------------------------------------------
__device__ __forceinline__ u64 fma2(u64 a, u64 b, u64 c) {
    u64 d; asm("fma.rn.f32x2 %0,%1,%2,%3;" : "=l"(d) : "l"(a), "l"(b), "l"(c)); return d;
}
__device__ __forceinline__ u64 mul2(u64 a, u64 b) {
    u64 d; asm("mul.rn.f32x2 %0,%1,%2;" : "=l"(d) : "l"(a), "l"(b)); return d;
}
__device__ __forceinline__ u64 add2(u64 a, u64 b) {
    u64 d; asm("add.rn.f32x2 %0,%1,%2;" : "=l"(d) : "l"(a), "l"(b)); return d;
}
__device__ __forceinline__ u64 pk2(float lo, float hi) {
    u64 d; asm("mov.b64 %0,{%1,%2};" : "=l"(d) : "f"(lo), "f"(hi)); return d;
}
__device__ __forceinline__ void upk2(u64 v, float& lo, float& hi) {
    asm("mov.b64 {%0,%1},%2;" : "=f"(lo), "=f"(hi) : "l"(v));
}

// ------------------------------------------------------------------
// Pass kernel (one routing round): accumulate per-chunk partial
//   s[b][o][j] = sum_{n in chunk} c[b][n][o] * u_hat[b][n][o][j]
// u_hat recomputed on the fly; c = softmax_o(u_hat . vsum) (round>0),
// uniform 0.1 (round 0, folded in at writeout).
//
// Threads: t in [0,320): p = t%160 (oj slot: o=p/16, j=p%16),
//          h = t/160 -> batch pairs [8h, 8h+8).
// Pipelining: W[n+1]/x[n+1] LDG issued at iter top into regs,
// STS into the alternate SMEM buffer overlapped with the r_s phase.
// ------------------------------------------------------------------
template<int ROUND>
__global__ void __launch_bounds__(NT, 2)
pass_kernel(const float* __restrict__ x, const float* __restrict__ W)
{
    const int nc = blockIdx.x;
    const int b0 = blockIdx.y * BT;
    const int t  = threadIdx.x;
    const int p  = t % OJ;
    const int h  = t / OJ;
    const int o  = p >> 4;
    const int ro = t >> 5;          // reduce phase: o (0..9 exact)
    const int rb = t & 31;          // reduce phase: b

    // W store mapping: float4 index t covers W[n][o][i][j..j+3]
    const int wi   = (t >> 2) & 7;              // i
    const int wcol = (t >> 5) * 16 + (t & 3) * 4; // o*16 + j

    // x load mapping (t<64): b = t/2, half = t&1
    const int xb = t >> 1;
    const int xh = t & 1;

    __shared__ __align__(16) u64   W2s[2][DIN][OJ + 1]; // [buf][i][oj]={w,w} 20.1KB
    __shared__ __align__(16) float x2f[2][DIN][BT];     // [buf][i][b]        2KB
    __shared__ __align__(16) float p_s[OJ][BT + 2];     // agreement partials 21.25KB
    __shared__ __align__(16) float e_s[NOUT][BT];       // exp(agreement)
    __shared__ __align__(16) float r_s[BT];             // 1/sum_o exp

    const float4* __restrict__ Wg = reinterpret_cast<const float4*>(W);
    const float4* __restrict__ xrow =
        reinterpret_cast<const float4*>(x + (size_t)(b0 + xb) * NIN * DIN);

    u64 s2[8];
    #pragma unroll
    for (int k = 0; k < 8; ++k) s2[k] = 0ULL;

    u64 vs2[8];
    if (ROUND > 0) {
        #pragma unroll
        for (int k = 0; k < 8; ++k) {
            const int b = b0 + 2 * (h * 8 + k);
            vs2[k] = pk2(g_vsum[b][p], g_vsum[b + 1][p]);
        }
    }

    const int nbase = nc * NPER;

    // ---- prologue: load + stage n=0 into buffer 0 ----
    float4 w4 = Wg[(size_t)nbase * 320 + t];
    float4 xv;
    if (t < 64) xv = xrow[(size_t)nbase * 2 + xh];
    W2s[0][wi][wcol + 0] = pk2(w4.x, w4.x);
    W2s[0][wi][wcol + 1] = pk2(w4.y, w4.y);
    W2s[0][wi][wcol + 2] = pk2(w4.z, w4.z);
    W2s[0][wi][wcol + 3] = pk2(w4.w, w4.w);
    if (t < 64) {
        x2f[0][xh * 4 + 0][xb] = xv.x;
        x2f[0][xh * 4 + 1][xb] = xv.y;
        x2f[0][xh * 4 + 2][xb] = xv.z;
        x2f[0][xh * 4 + 3][xb] = xv.w;
    }
    __syncthreads();

    for (int nn = 0; nn < NPER; ++nn) {
        const int buf  = nn & 1;
        const int nbuf = buf ^ 1;

        // ---- prefetch n+1 (clamped) into registers ----
        const int n1 = nbase + ((nn + 1 < NPER) ? nn + 1 : nn);
        w4 = Wg[(size_t)n1 * 320 + t];
        if (t < 64) xv = xrow[(size_t)n1 * 2 + xh];

        // ---- u_hat for this oj over 8 batch pairs (packed f32x2) ----
        u64 u2[8];
        #pragma unroll
        for (int k = 0; k < 8; ++k) u2[k] = 0ULL;
        #pragma unroll
        for (int i = 0; i < 8; ++i) {
            const u64 wr = W2s[buf][i][p];
            const ulonglong2* xp =
                reinterpret_cast<const ulonglong2*>(&x2f[buf][i][h * 16]);
            #pragma unroll
            for (int q = 0; q < 4; ++q) {
                ulonglong2 xq = xp[q];
                u2[2 * q]     = fma2(wr, xq.x, u2[2 * q]);
                u2[2 * q + 1] = fma2(wr, xq.y, u2[2 * q + 1]);
            }
        }

        if (ROUND == 0) {
            #pragma unroll
            for (int k = 0; k < 8; ++k) s2[k] = add2(s2[k], u2[k]);
            // stage n+1 into the other buffer
            W2s[nbuf][wi][wcol + 0] = pk2(w4.x, w4.x);
            W2s[nbuf][wi][wcol + 1] = pk2(w4.y, w4.y);
            W2s[nbuf][wi][wcol + 2] = pk2(w4.z, w4.z);
            W2s[nbuf][wi][wcol + 3] = pk2(w4.w, w4.w);
            if (t < 64) {
                x2f[nbuf][xh * 4 + 0][xb] = xv.x;
                x2f[nbuf][xh * 4 + 1][xb] = xv.y;
                x2f[nbuf][xh * 4 + 2][xb] = xv.z;
                x2f[nbuf][xh * 4 + 3][xb] = xv.w;
            }
            __syncthreads();
        } else {
            // ---- agreement partial products ----
            #pragma unroll
            for (int k = 0; k < 8; ++k)
                *reinterpret_cast<u64*>(&p_s[p][2 * (h * 8 + k)]) =
                    mul2(u2[k], vs2[k]);
            __syncthreads();

            // ---- reduce over j + exp; (ro,rb) covers 10x32 exactly ----
            {
                float a = 0.f;
                #pragma unroll
                for (int j = 0; j < 16; ++j) a += p_s[ro * 16 + j][rb];
                e_s[ro][rb] = __expf(a);   // |a| tiny -> matches max-shifted softmax
            }
            __syncthreads();

            // ---- r_s by one warp; everyone else stages n+1 under it ----
            if (t < BT) {
                float ssum = 0.f;
                #pragma unroll
                for (int oo = 0; oo < NOUT; ++oo) ssum += e_s[oo][t];
                r_s[t] = 1.0f / ssum;
            }
            W2s[nbuf][wi][wcol + 0] = pk2(w4.x, w4.x);
            W2s[nbuf][wi][wcol + 1] = pk2(w4.y, w4.y);
            W2s[nbuf][wi][wcol + 2] = pk2(w4.z, w4.z);
            W2s[nbuf][wi][wcol + 3] = pk2(w4.w, w4.w);
            if (t < 64) {
                x2f[nbuf][xh * 4 + 0][xb] = xv.x;
                x2f[nbuf][xh * 4 + 1][xb] = xv.y;
                x2f[nbuf][xh * 4 + 2][xb] = xv.z;
                x2f[nbuf][xh * 4 + 3][xb] = xv.w;
            }
            __syncthreads();

            // ---- reweight: s += c * u_hat ----
            #pragma unroll
            for (int k = 0; k < 8; ++k) {
                const int bp2 = 2 * (h * 8 + k);
                u64 ev = *reinterpret_cast<const u64*>(&e_s[o][bp2]);
                u64 rv = *reinterpret_cast<const u64*>(&r_s[bp2]);
                s2[k] = fma2(mul2(ev, rv), u2[k], s2[k]);
            }
            // no trailing barrier: next writes to e_s/r_s/p_s are all
            // separated from these reads by >=1 barrier in the next iter.
        }
    }

    // ---- write per-chunk partial (deterministic, no atomics) ----
    const float scale = (ROUND == 0) ? 0.1f : 1.0f;
    #pragma unroll
    for (int k = 0; k < 8; ++k) {
        const int b = b0 + 2 * (h * 8 + k);
        float lo, hi;
        upk2(s2[k], lo, hi);
        g_partial[nc][b][p]     = lo * scale;
        g_partial[nc][b + 1][p] = hi * scale;
    }
}

// ------------------------------------------------------------------
// Squash: reduce 36 chunk partials (3-way thread split for MLP),
// squash per (b,o), maintain cumulative vsum / emit final output.
// ------------------------------------------------------------------
template<int ROUND>
__global__ void __launch_bounds__(3 * OJ)
squash_kernel(float* __restrict__ out)
{
    const int b  = blockIdx.x;
    const int t  = threadIdx.x;
    const int g  = t / OJ;          // 0..2
    const int tt = t % OJ;

    __shared__ float red[3][OJ];

    float s = 0.f;
    #pragma unroll
    for (int c = 0; c < NCH / 3; ++c) s += g_partial[c * 3 + g][b][tt];
    red[g][tt] = s;
    __syncthreads();

    if (t < OJ) {
        const float sv = red[0][t] + red[1][t] + red[2][t];

        float nsq = sv * sv;
        #pragma unroll
        for (int m = 1; m < 16; m <<= 1)
            nsq += __shfl_xor_sync(0xffffffffu, nsq, m);

        const float norm = sqrtf(nsq + 1e-9f);
        const float v = sv * (nsq / ((1.0f + nsq) * norm));

        if (ROUND == 0)       g_vsum[b][t] = v;
        else if (ROUND == 1)  g_vsum[b][t] += v;
        else                  out[(size_t)b * OJ + t] = v;
    }
}

// ------------------------------------------------------------------
extern "C" void kernel_launch(void* const* d_in, const int* in_sizes, int n_in,
                              void* d_out, int out_size)
{
    const float* a0 = (const float*)d_in[0];
    const float* a1 = (const float*)d_in[1];
    const float* x;
    const float* W;
    if (in_sizes[0] == B * NIN * DIN) { x = a0; W = a1; }
    else                              { x = a1; W = a0; }
    float* out = (float*)d_out;

    dim3 pg(NCH, B / BT);   // 36 x 8 = 288 CTAs

    pass_kernel<0><<<pg, NT>>>(x, W);
    squash_kernel<0><<<B, 3 * OJ>>>(out);
    pass_kernel<1><<<pg, NT>>>(x, W);
    squash_kernel<1><<<B, 3 * OJ>>>(out);
    pass_kernel<2><<<pg, NT>>>(x, W);
    squash_kernel<2><<<B, 3 * OJ>>>(out);
}

// round 7
// speedup vs baseline: 1.1460x; 1.0387x over previous
#include <cuda_runtime.h>
#include <cstdint>
#include <cstddef>

#define B       256
#define NIN     1152
#define NOUT    10
#define DOUT    16
#define DIN     8
#define OJ      160        // NOUT*DOUT
#define BT      32         // batch tile per CTA
#define NCH     36         // n-chunks
#define NPER    32         // NIN / NCH
#define NT      160        // pass kernel threads (5 warps)

typedef unsigned long long u64;

// ------------------------------------------------------------------
// scratch (no allocations allowed -> __device__ globals)
// ------------------------------------------------------------------
__device__ float g_partial[NCH][B][OJ];   // per-chunk partial s (5.9 MB)
__device__ float g_vsum[B][OJ];           // cumulative v over rounds

// ------------------------------------------------------------------
// packed f32x2 helpers (sm_100+)
// ------------------------------------------------------------------
__device__ __forceinline__ u64 fma2(u64 a, u64 b, u64 c) {
    u64 d; asm("fma.rn.f32x2 %0,%1,%2,%3;" : "=l"(d) : "l"(a), "l"(b), "l"(c)); return d;
}
__device__ __forceinline__ u64 mul2(u64 a, u64 b) {
    u64 d; asm("mul.rn.f32x2 %0,%1,%2;" : "=l"(d) : "l"(a), "l"(b)); return d;
}
__device__ __forceinline__ u64 add2(u64 a, u64 b) {
    u64 d; asm("add.rn.f32x2 %0,%1,%2;" : "=l"(d) : "l"(a), "l"(b)); return d;
}
__device__ __forceinline__ u64 pk2(float lo, float hi) {
    u64 d; asm("mov.b64 %0,{%1,%2};" : "=l"(d) : "f"(lo), "f"(hi)); return d;
}
__device__ __forceinline__ void upk2(u64 v, float& lo, float& hi) {
    asm("mov.b64 {%0,%1},%2;" : "=f"(lo), "=f"(hi) : "l"(v));
}

// ------------------------------------------------------------------
// Pass kernel (one routing round), 160 threads:
//   t = h*80 + q*16 + j   (h: batch half, q in [0,5), j in [0,16))
//   thread owns oj slots p0 = 32q + j (o=2q) and p1 = p0+16 (o=2q+1),
//   and 16 batch elements (8 f32x2 pairs) [b0+16h, b0+16h+16).
// Per iter: 128 fma2 fed by 32 LDS.128 (x) + 16 LDS.64 (W) -> 4:1 reuse.
// W[n+1]/x[n+1] prefetched via LDG at iter top, staged into the
// alternate SMEM buffer late in the iteration.
// ------------------------------------------------------------------
template<int ROUND>
__global__ void __launch_bounds__(NT, 3)
pass_kernel(const float* __restrict__ x, const float* __restrict__ W)
{
    const int nc = blockIdx.x;
    const int b0 = blockIdx.y * BT;
    const int t  = threadIdx.x;
    const int j  = t & 15;
    const int q  = (t >> 4) % 5;
    const int h  = t / 80;
    const int p0 = q * 32 + j;          // o = 2q
    const int p1 = p0 + 16;             // o = 2q+1
    const int o0 = 2 * q;
    const int o1 = 2 * q + 1;

    // W staging mapping: thread loads float4 at [n*320 + t] and [n*320 + t + 160]
    //   flat float idx 4t   -> oA = t/32 (0..4), iA = (t>>2)&7, jA = (t&3)*4
    //   flat 4t + 2560      -> oA+5, same iA/jA
    const int wiA = (t >> 2) & 7;
    const int wcA = (t >> 5) * 16 + (t & 3) * 4;   // oA*16 + jA
    // x staging (t<64): b = t/2, half = t&1
    const int xb = t >> 1;
    const int xh = t & 1;

    __shared__ __align__(16) u64   W2s[2][DIN][OJ + 2]; // [buf][i][oj]={w,w} 20.25KB
    __shared__ __align__(16) float x2f[2][DIN][BT];     // [buf][i][b]         2KB
    __shared__ __align__(16) float p_s[OJ][BT + 2];     // agreement partials 21.25KB
    __shared__ __align__(16) float e_s[NOUT][BT];       // exp(agreement)
    __shared__ __align__(16) float r_s[BT];             // 1/sum_o exp

    const float4* __restrict__ Wg = reinterpret_cast<const float4*>(W);
    const float4* __restrict__ xrow =
        reinterpret_cast<const float4*>(x + (size_t)(b0 + xb) * NIN * DIN);

    u64 s2a[8], s2b[8];
    #pragma unroll
    for (int k = 0; k < 8; ++k) { s2a[k] = 0ULL; s2b[k] = 0ULL; }

    u64 vs2a[8], vs2b[8];
    if (ROUND > 0) {
        #pragma unroll
        for (int k = 0; k < 8; ++k) {
            const int b = b0 + 2 * (h * 8 + k);
            vs2a[k] = pk2(g_vsum[b][p0], g_vsum[b + 1][p0]);
            vs2b[k] = pk2(g_vsum[b][p1], g_vsum[b + 1][p1]);
        }
    }

    const int nbase = nc * NPER;

    // ---- prologue: load + stage n=0 into buffer 0 ----
    float4 w4a = Wg[(size_t)nbase * 320 + t];
    float4 w4b = Wg[(size_t)nbase * 320 + t + 160];
    float4 xv;
    if (t < 64) xv = xrow[(size_t)nbase * 2 + xh];
    {
        ulonglong2* wpA = reinterpret_cast<ulonglong2*>(&W2s[0][wiA][wcA]);
        ulonglong2* wpB = reinterpret_cast<ulonglong2*>(&W2s[0][wiA][wcA + 80]);
        wpA[0] = make_ulonglong2(pk2(w4a.x, w4a.x), pk2(w4a.y, w4a.y));
        wpA[1] = make_ulonglong2(pk2(w4a.z, w4a.z), pk2(w4a.w, w4a.w));
        wpB[0] = make_ulonglong2(pk2(w4b.x, w4b.x), pk2(w4b.y, w4b.y));
        wpB[1] = make_ulonglong2(pk2(w4b.z, w4b.z), pk2(w4b.w, w4b.w));
        if (t < 64) {
            x2f[0][xh * 4 + 0][xb] = xv.x;
            x2f[0][xh * 4 + 1][xb] = xv.y;
            x2f[0][xh * 4 + 2][xb] = xv.z;
            x2f[0][xh * 4 + 3][xb] = xv.w;
        }
    }
    __syncthreads();

    for (int nn = 0; nn < NPER; ++nn) {
        const int buf  = nn & 1;
        const int nbuf = buf ^ 1;

        // ---- prefetch n+1 (clamped) into registers ----
        const int n1 = nbase + ((nn + 1 < NPER) ? nn + 1 : nn);
        w4a = Wg[(size_t)n1 * 320 + t];
        w4b = Wg[(size_t)n1 * 320 + t + 160];
        if (t < 64) xv = xrow[(size_t)n1 * 2 + xh];

        // ---- u_hat for p0,p1 over 8 batch pairs ----
        u64 u2a[8], u2b[8];
        #pragma unroll
        for (int k = 0; k < 8; ++k) { u2a[k] = 0ULL; u2b[k] = 0ULL; }
        #pragma unroll
        for (int i = 0; i < 8; ++i) {
            const u64 w0 = W2s[buf][i][p0];
            const u64 w1 = W2s[buf][i][p1];
            const ulonglong2* xp =
                reinterpret_cast<const ulonglong2*>(&x2f[buf][i][h * 16]);
            #pragma unroll
            for (int qq = 0; qq < 4; ++qq) {
                ulonglong2 xq = xp[qq];
                u2a[2 * qq]     = fma2(w0, xq.x, u2a[2 * qq]);
                u2a[2 * qq + 1] = fma2(w0, xq.y, u2a[2 * qq + 1]);
                u2b[2 * qq]     = fma2(w1, xq.x, u2b[2 * qq]);
                u2b[2 * qq + 1] = fma2(w1, xq.y, u2b[2 * qq + 1]);
            }
        }

        if (ROUND == 0) {
            #pragma unroll
            for (int k = 0; k < 8; ++k) {
                s2a[k] = add2(s2a[k], u2a[k]);
                s2b[k] = add2(s2b[k], u2b[k]);
            }
            // stage n+1
            ulonglong2* wpA = reinterpret_cast<ulonglong2*>(&W2s[nbuf][wiA][wcA]);
            ulonglong2* wpB = reinterpret_cast<ulonglong2*>(&W2s[nbuf][wiA][wcA + 80]);
            wpA[0] = make_ulonglong2(pk2(w4a.x, w4a.x), pk2(w4a.y, w4a.y));
            wpA[1] = make_ulonglong2(pk2(w4a.z, w4a.z), pk2(w4a.w, w4a.w));
            wpB[0] = make_ulonglong2(pk2(w4b.x, w4b.x), pk2(w4b.y, w4b.y));
            wpB[1] = make_ulonglong2(pk2(w4b.z, w4b.z), pk2(w4b.w, w4b.w));
            if (t < 64) {
                x2f[nbuf][xh * 4 + 0][xb] = xv.x;
                x2f[nbuf][xh * 4 + 1][xb] = xv.y;
                x2f[nbuf][xh * 4 + 2][xb] = xv.z;
                x2f[nbuf][xh * 4 + 3][xb] = xv.w;
            }
            __syncthreads();
        } else {
            // ---- agreement partial products -> p_s ----
            #pragma unroll
            for (int k = 0; k < 8; ++k) {
                const int bp2 = 2 * (h * 8 + k);
                *reinterpret_cast<u64*>(&p_s[p0][bp2]) = mul2(u2a[k], vs2a[k]);
                *reinterpret_cast<u64*>(&p_s[p1][bp2]) = mul2(u2b[k], vs2b[k]);
            }
            __syncthreads();

            // ---- reduce over j + exp: thread -> o = t>>5 and (t>>5)+5, rb = t&31 ----
            {
                const int ro = t >> 5;
                const int rb = t & 31;
                float a0 = 0.f, a1 = 0.f;
                #pragma unroll
                for (int jj = 0; jj < 16; ++jj) {
                    a0 += p_s[ro * 16 + jj][rb];
                    a1 += p_s[(ro + 5) * 16 + jj][rb];
                }
                e_s[ro][rb]     = __expf(a0);  // |a| tiny -> matches max-shifted softmax
                e_s[ro + 5][rb] = __expf(a1);
            }
            __syncthreads();

            // ---- r_s by warp 0; everyone stages n+1 under it ----
            if (t < BT) {
                float ssum = 0.f;
                #pragma unroll
                for (int oo = 0; oo < NOUT; ++oo) ssum += e_s[oo][t];
                r_s[t] = 1.0f / ssum;
            }
            {
                ulonglong2* wpA = reinterpret_cast<ulonglong2*>(&W2s[nbuf][wiA][wcA]);
                ulonglong2* wpB = reinterpret_cast<ulonglong2*>(&W2s[nbuf][wiA][wcA + 80]);
                wpA[0] = make_ulonglong2(pk2(w4a.x, w4a.x), pk2(w4a.y, w4a.y));
                wpA[1] = make_ulonglong2(pk2(w4a.z, w4a.z), pk2(w4a.w, w4a.w));
                wpB[0] = make_ulonglong2(pk2(w4b.x, w4b.x), pk2(w4b.y, w4b.y));
                wpB[1] = make_ulonglong2(pk2(w4b.z, w4b.z), pk2(w4b.w, w4b.w));
                if (t < 64) {
                    x2f[nbuf][xh * 4 + 0][xb] = xv.x;
                    x2f[nbuf][xh * 4 + 1][xb] = xv.y;
                    x2f[nbuf][xh * 4 + 2][xb] = xv.z;
                    x2f[nbuf][xh * 4 + 3][xb] = xv.w;
                }
            }
            __syncthreads();

            // ---- reweight: s += c * u_hat ----
            #pragma unroll
            for (int k = 0; k < 8; ++k) {
                const int bp2 = 2 * (h * 8 + k);
                u64 rv = *reinterpret_cast<const u64*>(&r_s[bp2]);
                u64 e0 = *reinterpret_cast<const u64*>(&e_s[o0][bp2]);
                u64 e1 = *reinterpret_cast<const u64*>(&e_s[o1][bp2]);
                s2a[k] = fma2(mul2(e0, rv), u2a[k], s2a[k]);
                s2b[k] = fma2(mul2(e1, rv), u2b[k], s2b[k]);
            }
            // no trailing barrier: all shared reads here are separated from the
            // next writers (p_s/e_s/r_s/W2s[nbuf]) by >=1 barrier next iteration.
        }
    }

    // ---- write per-chunk partial (deterministic, no atomics) ----
    const float scale = (ROUND == 0) ? 0.1f : 1.0f;
    #pragma unroll
    for (int k = 0; k < 8; ++k) {
        const int b = b0 + 2 * (h * 8 + k);
        float lo, hi;
        upk2(s2a[k], lo, hi);
        g_partial[nc][b][p0]     = lo * scale;
        g_partial[nc][b + 1][p0] = hi * scale;
        upk2(s2b[k], lo, hi);
        g_partial[nc][b][p1]     = lo * scale;
        g_partial[nc][b + 1][p1] = hi * scale;
    }
}

// ------------------------------------------------------------------
// Squash: one (b,oj) output per thread, 36 fully-independent LDGs
// (MLP=36), 16-lane shfl for the j-norm. 160 blocks x 256 threads.
// ------------------------------------------------------------------
template<int ROUND>
__global__ void __launch_bounds__(256)
squash_kernel(float* __restrict__ out)
{
    const int g = blockIdx.x * 256 + threadIdx.x;   // [0, 40960)
    const float* gp = &g_partial[0][0][0];

    float s = 0.f;
    #pragma unroll
    for (int c = 0; c < NCH; ++c) s += gp[(size_t)c * (B * OJ) + g];

    // 16-lane groups share (b,o); j = low 4 bits of lane (16 | 160, 16 | 256)
    float nsq = s * s;
    #pragma unroll
    for (int m = 1; m < 16; m <<= 1)
        nsq += __shfl_xor_sync(0xffffffffu, nsq, m);

    const float norm = sqrtf(nsq + 1e-9f);
    const float v = s * (nsq / ((1.0f + nsq) * norm));

    float* vs = &g_vsum[0][0];
    if (ROUND == 0)       vs[g] = v;
    else if (ROUND == 1)  vs[g] += v;
    else                  out[g] = v;
}

// ------------------------------------------------------------------
// no-op launch: shifts the ncu -s/-c capture window onto pass_kernel<1>
// ------------------------------------------------------------------
__global__ void noop_kernel() {}

// ------------------------------------------------------------------
extern "C" void kernel_launch(void* const* d_in, const int* in_sizes, int n_in,
                              void* d_out, int out_size)
{
    const float* a0 = (const float*)d_in[0];
    const float* a1 = (const float*)d_in[1];
    const float* x;
    const float* W;
    if (in_sizes[0] == B * NIN * DIN) { x = a0; W = a1; }
    else                              { x = a1; W = a0; }
    float* out = (float*)d_out;

    dim3 pg(NCH, B / BT);   // 36 x 8 = 288 CTAs

    noop_kernel<<<1, 32>>>();
    pass_kernel<0><<<pg, NT>>>(x, W);
    squash_kernel<0><<<160, 256>>>(out);
    pass_kernel<1><<<pg, NT>>>(x, W);
    squash_kernel<1><<<160, 256>>>(out);
    pass_kernel<2><<<pg, NT>>>(x, W);
    squash_kernel<2><<<160, 256>>>(out);
}